// round 2
// baseline (speedup 1.0000x reference)
#include <cuda_runtime.h>

// Embedder: multirate zero-insert upsample -> conv1d(1->256, K=5, same) -> gather.
// Collapses to closed-form per-stream FIR taps:
//   stream0 (s=4): out[p] = b + w2*x250[p]                      (p<15000, else 0)
//   stream1 (s=2): out[p] = b + w0*x500[p-1]+w2*x500[p]+w4*x500[p+1] (p<30000, else 0)
//   stream2 (s=1): full 5-tap 'same' correlation over x1000
// Output = X[3,256,60000] ++ S[2,60000], 46.2M floats (~185 MB). Store-dominated.
//
// R2: warp-contiguous row layout. 1 vectorized LDG.128 per thread + shfl halo
// instead of 6-8 scalar LDGs -> halves load-side L1TEX wavefronts.

#define L250   15000
#define L500   30000
#define L1000  60000
#define ROW4   15000                  // float4 per (stream,d) row
#define NROWS  768                    // 3 * 256
#define X4TOT  (NROWS * ROW4)         // 11,520,000 float4
#define S4TOT  30000                  // 2*60000/4
#define CHUNK4 1024                   // float4 per block (8 warps * 4 iters * 32)
#define BPR    15                     // ceil(15000/1024)
#define XBLOCKS (NROWS * BPR)         // 11,520
#define SBLOCKS ((S4TOT + 255) / 256) // 118

__device__ __forceinline__ float ldx(const float* __restrict__ x, int i, int l) {
    return (i >= 0 && i < l) ? __ldg(x + i) : 0.0f;
}

__global__ void __launch_bounds__(256)
embedder_kernel(const float* __restrict__ x250,
                const float* __restrict__ x500,
                const float* __restrict__ x1000,
                const float* __restrict__ W,   // [256,1,5]
                const float* __restrict__ b,   // [256]
                float4* __restrict__ out)
{
    const unsigned FULL = 0xffffffffu;
    int blk = blockIdx.x;

    if (blk < XBLOCKS) {
        int row    = blk / BPR;
        int chunk  = blk - row * BPR;
        int stream = row >> 8;
        int d      = row & 255;
        int lane   = threadIdx.x & 31;
        int warp   = threadIdx.x >> 5;

        float4* __restrict__ orow = out + (long)row * ROW4;
        int tbase = chunk * CHUNK4 + warp * 128 + lane;   // + j*32 per iter

        if (stream == 0) {
            float w2 = __ldg(W + d * 5 + 2);
            float bb = __ldg(b + d);
            const float4* __restrict__ xv = (const float4*)x250;
            #pragma unroll
            for (int j = 0; j < 4; j++) {
                int f4 = tbase + j * 32;
                float4 o = make_float4(0.f, 0.f, 0.f, 0.f);
                if (f4 < 3750) {                      // p < 15000
                    float4 c = xv[f4];
                    o.x = fmaf(w2, c.x, bb);
                    o.y = fmaf(w2, c.y, bb);
                    o.z = fmaf(w2, c.z, bb);
                    o.w = fmaf(w2, c.w, bb);
                }
                if (f4 < ROW4) orow[f4] = o;
            }
        } else if (stream == 1) {
            float w0 = __ldg(W + d * 5 + 0);
            float w2 = __ldg(W + d * 5 + 2);
            float w4 = __ldg(W + d * 5 + 4);
            float bb = __ldg(b + d);
            const float4* __restrict__ xv = (const float4*)x500;
            #pragma unroll
            for (int j = 0; j < 4; j++) {
                int f4 = tbase + j * 32;
                int wbase = f4 - lane;                // warp-uniform
                float4 o = make_float4(0.f, 0.f, 0.f, 0.f);
                if (wbase < 7500) {                   // warp has active lanes
                    bool act = (f4 < 7500);
                    float4 c = act ? xv[f4] : make_float4(0.f, 0.f, 0.f, 0.f);
                    float pw = __shfl_up_sync(FULL, c.w, 1);   // x[4f4-1]
                    float nx = __shfl_down_sync(FULL, c.x, 1); // x[4f4+4]
                    if (lane == 0)  pw = ldx(x500, 4 * f4 - 1, L500);
                    if (lane == 31) nx = ldx(x500, 4 * f4 + 4, L500);
                    if (act) {
                        o.x = fmaf(w0, pw,  fmaf(w2, c.x, fmaf(w4, c.y, bb)));
                        o.y = fmaf(w0, c.x, fmaf(w2, c.y, fmaf(w4, c.z, bb)));
                        o.z = fmaf(w0, c.y, fmaf(w2, c.z, fmaf(w4, c.w, bb)));
                        o.w = fmaf(w0, c.z, fmaf(w2, c.w, fmaf(w4, nx,  bb)));
                    }
                }
                if (f4 < ROW4) orow[f4] = o;
            }
        } else {
            float w0 = __ldg(W + d * 5 + 0);
            float w1 = __ldg(W + d * 5 + 1);
            float w2 = __ldg(W + d * 5 + 2);
            float w3 = __ldg(W + d * 5 + 3);
            float w4 = __ldg(W + d * 5 + 4);
            float bb = __ldg(b + d);
            const float4* __restrict__ xv = (const float4*)x1000;
            #pragma unroll
            for (int j = 0; j < 4; j++) {
                int f4 = tbase + j * 32;
                bool act = (f4 < ROW4);
                float4 c = act ? xv[f4] : make_float4(0.f, 0.f, 0.f, 0.f);
                float pz = __shfl_up_sync(FULL, c.z, 1);   // x[4f4-2]
                float pw = __shfl_up_sync(FULL, c.w, 1);   // x[4f4-1]
                float nx = __shfl_down_sync(FULL, c.x, 1); // x[4f4+4]
                float ny = __shfl_down_sync(FULL, c.y, 1); // x[4f4+5]
                if (lane == 0) {
                    pz = ldx(x1000, 4 * f4 - 2, L1000);
                    pw = ldx(x1000, 4 * f4 - 1, L1000);
                }
                if (lane == 31) {
                    nx = ldx(x1000, 4 * f4 + 4, L1000);
                    ny = ldx(x1000, 4 * f4 + 5, L1000);
                }
                if (act) {
                    float4 o;
                    o.x = fmaf(w0, pz,  fmaf(w1, pw,  fmaf(w2, c.x, fmaf(w3, c.y, fmaf(w4, c.z, bb)))));
                    o.y = fmaf(w0, pw,  fmaf(w1, c.x, fmaf(w2, c.y, fmaf(w3, c.z, fmaf(w4, c.w, bb)))));
                    o.z = fmaf(w0, c.x, fmaf(w1, c.y, fmaf(w2, c.z, fmaf(w3, c.w, fmaf(w4, nx,  bb)))));
                    o.w = fmaf(w0, c.y, fmaf(w1, c.z, fmaf(w2, c.w, fmaf(w3, nx,  fmaf(w4, ny,  bb)))));
                    orow[f4] = o;
                }
            }
        }
    } else {
        // S = [rows(60000), cols(60000)] as float
        int i = (blk - XBLOCKS) * 256 + threadIdx.x;
        if (i < S4TOT) {
            int e = i * 4;
            float4 o;
            float* po = (float*)&o;
            if (e < L1000) {
                float r = (e < L250) ? 0.f : ((e < L250 + L500) ? 1.f : 2.f);
                o = make_float4(r, r, r, r);
            } else {
                int p = e - L1000;
                #pragma unroll
                for (int t = 0; t < 4; t++) {
                    int q = p + t;
                    float c;
                    if (q < L250)             c = (float)(q * 4);
                    else if (q < L250 + L500) c = (float)((q - L250) * 2);
                    else                      c = (float)(q - (L250 + L500));
                    po[t] = c;
                }
            }
            out[X4TOT + i] = o;
        }
    }
}

extern "C" void kernel_launch(void* const* d_in, const int* in_sizes, int n_in,
                              void* d_out, int out_size) {
    const float* x250  = (const float*)d_in[0];
    const float* x500  = (const float*)d_in[1];
    const float* x1000 = (const float*)d_in[2];
    const float* W     = (const float*)d_in[3];
    const float* b     = (const float*)d_in[4];
    float4* out = (float4*)d_out;

    int blocks = XBLOCKS + SBLOCKS;
    embedder_kernel<<<blocks, 256>>>(x250, x500, x1000, W, b, out);
}

// round 4
// speedup vs baseline: 1.4378x; 1.4378x over previous
#include <cuda_runtime.h>

// Embedder: multirate zero-insert upsample -> conv1d(1->256, K=5, same) -> gather.
// Closed-form per-stream FIR taps. Output = X[3,256,60000] ++ S[2,60000] (~185 MB).
//
// R3 (resubmit after infra failure): d-reuse layout. Block = (stream, p-chunk of
// 256 float4, group of 64 d). Thread keeps its x window in REGISTERS across the
// d-loop; weights come from smem via broadcast LDS.64. Inner loop = lds + fma +
// stg only. Zero regions degenerate to pure store loops.

#define L250   15000
#define L500   30000
#define L1000  60000
#define ROW4   15000                       // float4 per (stream,d) row
#define X4TOT  (768 * ROW4)                // 11,520,000 float4
#define S4TOT  30000
#define NCH    59                          // ceil(15000 / 256)
#define NDG    4                           // 4 groups of 64 d
#define XBLOCKS (3 * NCH * NDG)            // 708
#define SBLOCKS ((S4TOT + 255) / 256)      // 118

__device__ __forceinline__ float ldx(const float* __restrict__ x, int i, int l) {
    return (i >= 0 && i < l) ? __ldg(x + i) : 0.0f;
}

__global__ void __launch_bounds__(256)
embedder_kernel(const float* __restrict__ x250,
                const float* __restrict__ x500,
                const float* __restrict__ x1000,
                const float* __restrict__ W,   // [256,1,5]
                const float* __restrict__ b,   // [256]
                float4* __restrict__ out)
{
    int blk = blockIdx.x;

    if (blk < XBLOCKS) {
        int stream = blk / (NCH * NDG);
        int rem    = blk - stream * (NCH * NDG);
        int chunk  = rem >> 2;                 // / NDG
        int g      = rem & 3;                  // % NDG
        int t      = threadIdx.x;

        __shared__ float sw[64][6];            // {w0,w1,w2,w3,w4,b} per d; rows 24B
        if (t < 64) {
            int d = g * 64 + t;
            #pragma unroll
            for (int k = 0; k < 5; k++) sw[t][k] = __ldg(W + d * 5 + k);
            sw[t][5] = __ldg(b + d);
        }
        __syncthreads();

        int f4 = chunk * 256 + t;
        if (f4 >= ROW4) return;
        int p = f4 * 4;

        float4* po = out + ((long)(stream * 256 + g * 64) * ROW4 + f4);
        const float4 ZZ = make_float4(0.f, 0.f, 0.f, 0.f);

        if (stream == 0) {
            if (f4 < 3750) {                  // p < 15000
                float4 c = __ldg((const float4*)x250 + f4);
                #pragma unroll 4
                for (int i = 0; i < 64; i++) {
                    float2 cd = *(const float2*)&sw[i][2];   // w2, w3
                    float2 ef = *(const float2*)&sw[i][4];   // w4, b
                    float w2 = cd.x, bb = ef.y;
                    float4 o;
                    o.x = fmaf(w2, c.x, bb);
                    o.y = fmaf(w2, c.y, bb);
                    o.z = fmaf(w2, c.z, bb);
                    o.w = fmaf(w2, c.w, bb);
                    __stcs(po, o);  po += ROW4;
                }
            } else {
                #pragma unroll 8
                for (int i = 0; i < 64; i++) { __stcs(po, ZZ); po += ROW4; }
            }
        } else if (stream == 1) {
            if (f4 < 7500) {                  // p < 30000
                float v0 = ldx(x500, p - 1, L500);
                float4 c = __ldg((const float4*)x500 + f4);
                float v5 = ldx(x500, p + 4, L500);
                #pragma unroll 4
                for (int i = 0; i < 64; i++) {
                    float2 ab = *(const float2*)&sw[i][0];   // w0, w1
                    float2 cd = *(const float2*)&sw[i][2];   // w2, w3
                    float2 ef = *(const float2*)&sw[i][4];   // w4, b
                    float w0 = ab.x, w2 = cd.x, w4 = ef.x, bb = ef.y;
                    float4 o;
                    o.x = fmaf(w0, v0,  fmaf(w2, c.x, fmaf(w4, c.y, bb)));
                    o.y = fmaf(w0, c.x, fmaf(w2, c.y, fmaf(w4, c.z, bb)));
                    o.z = fmaf(w0, c.y, fmaf(w2, c.z, fmaf(w4, c.w, bb)));
                    o.w = fmaf(w0, c.z, fmaf(w2, c.w, fmaf(w4, v5,  bb)));
                    __stcs(po, o);  po += ROW4;
                }
            } else {
                #pragma unroll 8
                for (int i = 0; i < 64; i++) { __stcs(po, ZZ); po += ROW4; }
            }
        } else {
            float u0 = ldx(x1000, p - 2, L1000);
            float u1 = ldx(x1000, p - 1, L1000);
            float4 c = __ldg((const float4*)x1000 + f4);
            float u6 = ldx(x1000, p + 4, L1000);
            float u7 = ldx(x1000, p + 5, L1000);
            #pragma unroll 4
            for (int i = 0; i < 64; i++) {
                float2 ab = *(const float2*)&sw[i][0];   // w0, w1
                float2 cd = *(const float2*)&sw[i][2];   // w2, w3
                float2 ef = *(const float2*)&sw[i][4];   // w4, b
                float4 o;
                o.x = fmaf(ab.x, u0,  fmaf(ab.y, u1,  fmaf(cd.x, c.x, fmaf(cd.y, c.y, fmaf(ef.x, c.z, ef.y)))));
                o.y = fmaf(ab.x, u1,  fmaf(ab.y, c.x, fmaf(cd.x, c.y, fmaf(cd.y, c.z, fmaf(ef.x, c.w, ef.y)))));
                o.z = fmaf(ab.x, c.x, fmaf(ab.y, c.y, fmaf(cd.x, c.z, fmaf(cd.y, c.w, fmaf(ef.x, u6,  ef.y)))));
                o.w = fmaf(ab.x, c.y, fmaf(ab.y, c.z, fmaf(cd.x, c.w, fmaf(cd.y, u6,  fmaf(ef.x, u7,  ef.y)))));
                __stcs(po, o);  po += ROW4;
            }
        }
    } else {
        // S = [rows(60000), cols(60000)] as float
        int i = (blk - XBLOCKS) * 256 + threadIdx.x;
        if (i < S4TOT) {
            int e = i * 4;
            float4 o;
            float* pf = (float*)&o;
            if (e < L1000) {
                float r = (e < L250) ? 0.f : ((e < L250 + L500) ? 1.f : 2.f);
                o = make_float4(r, r, r, r);
            } else {
                int p = e - L1000;
                #pragma unroll
                for (int k = 0; k < 4; k++) {
                    int q = p + k;
                    float cc;
                    if (q < L250)             cc = (float)(q * 4);
                    else if (q < L250 + L500) cc = (float)((q - L250) * 2);
                    else                      cc = (float)(q - (L250 + L500));
                    pf[k] = cc;
                }
            }
            __stcs(out + X4TOT + i, o);
        }
    }
}

extern "C" void kernel_launch(void* const* d_in, const int* in_sizes, int n_in,
                              void* d_out, int out_size) {
    const float* x250  = (const float*)d_in[0];
    const float* x500  = (const float*)d_in[1];
    const float* x1000 = (const float*)d_in[2];
    const float* W     = (const float*)d_in[3];
    const float* b     = (const float*)d_in[4];
    float4* out = (float4*)d_out;

    embedder_kernel<<<XBLOCKS + SBLOCKS, 256>>>(x250, x500, x1000, W, b, out);
}

// round 5
// speedup vs baseline: 1.5220x; 1.0585x over previous
#include <cuda_runtime.h>

// Embedder: multirate zero-insert upsample -> conv1d(1->256, K=5, same) -> gather.
// Closed-form per-stream FIR taps. Output = X[3,256,60000] ++ S[2,60000] (~185 MB).
//
// R5: same d-reuse design as R4 (thread keeps x window in registers, weights via
// smem broadcast, streaming stores), but d-group halved to 32 -> 1534 blocks for
// ~2x occupancy and better stream-imbalance smoothing.

#define L250   15000
#define L500   30000
#define L1000  60000
#define ROW4   15000                       // float4 per (stream,d) row
#define X4TOT  (768 * ROW4)                // 11,520,000 float4
#define S4TOT  30000
#define NCH    59                          // ceil(15000 / 256)
#define NDG    8                           // 8 groups of 32 d
#define DG     32
#define XBLOCKS (3 * NCH * NDG)            // 1416
#define SBLOCKS ((S4TOT + 255) / 256)      // 118

__device__ __forceinline__ float ldx(const float* __restrict__ x, int i, int l) {
    return (i >= 0 && i < l) ? __ldg(x + i) : 0.0f;
}

__global__ void __launch_bounds__(256)
embedder_kernel(const float* __restrict__ x250,
                const float* __restrict__ x500,
                const float* __restrict__ x1000,
                const float* __restrict__ W,   // [256,1,5]
                const float* __restrict__ b,   // [256]
                float4* __restrict__ out)
{
    int blk = blockIdx.x;

    if (blk < XBLOCKS) {
        int stream = blk / (NCH * NDG);
        int rem    = blk - stream * (NCH * NDG);
        int chunk  = rem >> 3;                 // / NDG
        int g      = rem & 7;                  // % NDG
        int t      = threadIdx.x;

        __shared__ float sw[DG][6];            // {w0,w1,w2,w3,w4,b} per d
        if (t < DG) {
            int d = g * DG + t;
            #pragma unroll
            for (int k = 0; k < 5; k++) sw[t][k] = __ldg(W + d * 5 + k);
            sw[t][5] = __ldg(b + d);
        }
        __syncthreads();

        int f4 = chunk * 256 + t;
        if (f4 >= ROW4) return;
        int p = f4 * 4;

        float4* po = out + ((long)(stream * 256 + g * DG) * ROW4 + f4);
        const float4 ZZ = make_float4(0.f, 0.f, 0.f, 0.f);

        if (stream == 0) {
            if (f4 < 3750) {                  // p < 15000
                float4 c = __ldg((const float4*)x250 + f4);
                #pragma unroll 4
                for (int i = 0; i < DG; i++) {
                    float2 cd = *(const float2*)&sw[i][2];   // w2, w3
                    float2 ef = *(const float2*)&sw[i][4];   // w4, b
                    float w2 = cd.x, bb = ef.y;
                    float4 o;
                    o.x = fmaf(w2, c.x, bb);
                    o.y = fmaf(w2, c.y, bb);
                    o.z = fmaf(w2, c.z, bb);
                    o.w = fmaf(w2, c.w, bb);
                    __stcs(po, o);  po += ROW4;
                }
            } else {
                #pragma unroll 8
                for (int i = 0; i < DG; i++) { __stcs(po, ZZ); po += ROW4; }
            }
        } else if (stream == 1) {
            if (f4 < 7500) {                  // p < 30000
                float v0 = ldx(x500, p - 1, L500);
                float4 c = __ldg((const float4*)x500 + f4);
                float v5 = ldx(x500, p + 4, L500);
                #pragma unroll 4
                for (int i = 0; i < DG; i++) {
                    float2 ab = *(const float2*)&sw[i][0];
                    float2 cd = *(const float2*)&sw[i][2];
                    float2 ef = *(const float2*)&sw[i][4];
                    float w0 = ab.x, w2 = cd.x, w4 = ef.x, bb = ef.y;
                    float4 o;
                    o.x = fmaf(w0, v0,  fmaf(w2, c.x, fmaf(w4, c.y, bb)));
                    o.y = fmaf(w0, c.x, fmaf(w2, c.y, fmaf(w4, c.z, bb)));
                    o.z = fmaf(w0, c.y, fmaf(w2, c.z, fmaf(w4, c.w, bb)));
                    o.w = fmaf(w0, c.z, fmaf(w2, c.w, fmaf(w4, v5,  bb)));
                    __stcs(po, o);  po += ROW4;
                }
            } else {
                #pragma unroll 8
                for (int i = 0; i < DG; i++) { __stcs(po, ZZ); po += ROW4; }
            }
        } else {
            float u0 = ldx(x1000, p - 2, L1000);
            float u1 = ldx(x1000, p - 1, L1000);
            float4 c = __ldg((const float4*)x1000 + f4);
            float u6 = ldx(x1000, p + 4, L1000);
            float u7 = ldx(x1000, p + 5, L1000);
            #pragma unroll 4
            for (int i = 0; i < DG; i++) {
                float2 ab = *(const float2*)&sw[i][0];
                float2 cd = *(const float2*)&sw[i][2];
                float2 ef = *(const float2*)&sw[i][4];
                float4 o;
                o.x = fmaf(ab.x, u0,  fmaf(ab.y, u1,  fmaf(cd.x, c.x, fmaf(cd.y, c.y, fmaf(ef.x, c.z, ef.y)))));
                o.y = fmaf(ab.x, u1,  fmaf(ab.y, c.x, fmaf(cd.x, c.y, fmaf(cd.y, c.z, fmaf(ef.x, c.w, ef.y)))));
                o.z = fmaf(ab.x, c.x, fmaf(ab.y, c.y, fmaf(cd.x, c.z, fmaf(cd.y, c.w, fmaf(ef.x, u6,  ef.y)))));
                o.w = fmaf(ab.x, c.y, fmaf(ab.y, c.z, fmaf(cd.x, c.w, fmaf(cd.y, u6,  fmaf(ef.x, u7,  ef.y)))));
                __stcs(po, o);  po += ROW4;
            }
        }
    } else {
        // S = [rows(60000), cols(60000)] as float
        int i = (blk - XBLOCKS) * 256 + threadIdx.x;
        if (i < S4TOT) {
            int e = i * 4;
            float4 o;
            float* pf = (float*)&o;
            if (e < L1000) {
                float r = (e < L250) ? 0.f : ((e < L250 + L500) ? 1.f : 2.f);
                o = make_float4(r, r, r, r);
            } else {
                int p = e - L1000;
                #pragma unroll
                for (int k = 0; k < 4; k++) {
                    int q = p + k;
                    float cc;
                    if (q < L250)             cc = (float)(q * 4);
                    else if (q < L250 + L500) cc = (float)((q - L250) * 2);
                    else                      cc = (float)(q - (L250 + L500));
                    pf[k] = cc;
                }
            }
            __stcs(out + X4TOT + i, o);
        }
    }
}

extern "C" void kernel_launch(void* const* d_in, const int* in_sizes, int n_in,
                              void* d_out, int out_size) {
    const float* x250  = (const float*)d_in[0];
    const float* x500  = (const float*)d_in[1];
    const float* x1000 = (const float*)d_in[2];
    const float* W     = (const float*)d_in[3];
    const float* b     = (const float*)d_in[4];
    float4* out = (float4*)d_out;

    embedder_kernel<<<XBLOCKS + SBLOCKS, 256>>>(x250, x500, x1000, W, b, out);
}